// round 8
// baseline (speedup 1.0000x reference)
#include <cuda_runtime.h>
#include <cuda_fp16.h>
#include <math.h>
#include <stdint.h>

#define B_  32
#define S_  2048
#define DH_ 1024
#define DF_ 1024
#define DM_ 512

// Scratch (no cudaMalloc allowed)
__device__ float  g_embh[B_ * DM_];     // emb_h + b1h + b1f
__device__ float  g_logits[B_ * S_];    // pre-softmax logits
__device__ __half g_w1f_h[DM_ * DF_];   // 1 MiB half copy of W1f

// ---------------------------------------------------------------------------
// Helpers
// ---------------------------------------------------------------------------
__device__ __forceinline__ void mma_f16(float c[4], const uint32_t a[4], const uint32_t b[2]) {
    asm volatile(
        "mma.sync.aligned.m16n8k16.row.col.f32.f16.f16.f32 "
        "{%0,%1,%2,%3}, {%4,%5,%6,%7}, {%8,%9}, {%0,%1,%2,%3};"
        : "+f"(c[0]), "+f"(c[1]), "+f"(c[2]), "+f"(c[3])
        : "r"(a[0]), "r"(a[1]), "r"(a[2]), "r"(a[3]),
          "r"(b[0]), "r"(b[1]));
}

__device__ __forceinline__ unsigned sptr(const void* p) {
    return (unsigned)__cvta_generic_to_shared(p);
}

__device__ __forceinline__ void ldsm_x4(uint32_t r[4], const void* p) {
    unsigned a = sptr(p);
    asm volatile("ldmatrix.sync.aligned.m8n8.x4.shared.b16 {%0,%1,%2,%3}, [%4];"
                 : "=r"(r[0]), "=r"(r[1]), "=r"(r[2]), "=r"(r[3]) : "r"(a));
}

__device__ __forceinline__ float tanh_fast(float x) {
    // tanh(x) = 1 - 2/(exp(2x)+1), via ex2/rcp approx (rel err ~1e-6).
    float e;
    asm("ex2.approx.f32 %0, %1;" : "=f"(e) : "f"(x * 2.8853900817779268f));
    float r;
    asm("rcp.approx.f32 %0, %1;" : "=f"(r) : "f"(e + 1.0f));
    return 1.0f - 2.0f * r;
}

__device__ __forceinline__ void cpasync16(unsigned dst, const void* src) {
    asm volatile("cp.async.cg.shared.global [%0], [%1], 16;\n" :: "r"(dst), "l"(src));
}
__device__ __forceinline__ void cpcommit() { asm volatile("cp.async.commit_group;\n"); }
template<int N> __device__ __forceinline__ void cpwait() {
    asm volatile("cp.async.wait_group %0;\n" :: "n"(N));
}

// ---------------------------------------------------------------------------
// fp32 -> fp16 conversion of W1f only (1 MiB; feats converted in-register)
// ---------------------------------------------------------------------------
__global__ __launch_bounds__(512) void cvt_w1f_kernel(const float4* __restrict__ src)
{
    const int n4 = (DM_ * DF_) / 4;
    uint2* dst = (uint2*)g_w1f_h;
    int stride = gridDim.x * blockDim.x;
    for (int i = blockIdx.x * blockDim.x + threadIdx.x; i < n4; i += stride) {
        float4 v = src[i];
        __half2 h0 = __floats2half2_rn(v.x, v.y);
        __half2 h1 = __floats2half2_rn(v.z, v.w);
        dst[i] = make_uint2(*(unsigned*)&h0, *(unsigned*)&h1);
    }
}

// ---------------------------------------------------------------------------
// Stage 0: emb_h[b,m] = hidden[b,:]·W1h[m,:] + b1h[m] + b1f[m]
// ---------------------------------------------------------------------------
__global__ __launch_bounds__(512) void embh_kernel(
    const float* __restrict__ hidden, const float* __restrict__ W1h,
    const float* __restrict__ b1h, const float* __restrict__ b1f)
{
    int b = blockIdx.x;
    __shared__ float h_s[DH_];
    for (int k = threadIdx.x; k < DH_; k += 512) h_s[k] = hidden[b * DH_ + k];
    __syncthreads();

    int wid = threadIdx.x >> 5, lane = threadIdx.x & 31;
    for (int j = 0; j < DM_ / 16; j++) {
        int m = wid * (DM_ / 16) + j;
        const float* w = W1h + (size_t)m * DH_;
        float acc = 0.f;
        #pragma unroll 8
        for (int k = lane; k < DH_; k += 32) acc += h_s[k] * w[k];
        #pragma unroll
        for (int o = 16; o; o >>= 1) acc += __shfl_xor_sync(0xFFFFFFFFu, acc, o);
        if (lane == 0) g_embh[b * DM_ + m] = acc + b1h[m] + b1f[m];
    }
}

// ---------------------------------------------------------------------------
// Stage 1: fused logits. Block = 128 (b,s) rows x all 512 DM cols.
// fp16 m16n8k16, ldmatrix fragment loads, cp.async double-buffered B (W1f),
// A (feats) read as fp32 via LDG and converted in-register.
// RACE-SAFE single-barrier pipeline (loads issued AFTER the barrier).
// 16 warps: warp_m {0,1} x warp_n {0..7}, warp tile 64x64 (C = 4x8x4 regs).
// ---------------------------------------------------------------------------
#define MT  128           // rows per block
#define KC  32
#define KPH 40            // padded row stride in halves (80 B, conflict-free)
#define NIT (DF_ / KC)    // 32

struct SmemL {
    __half As[2][MT][KPH];
    __half Bs[2][512][KPH];
    float  eh[DM_];
    float  w2s[DM_];
    float  logit[MT];
};

__device__ __forceinline__ void load_B(SmemL* sm, int stage, int kb, int tid) {
    // B tile: 512 rows x 32 halves = 2048 x 16B chunks, 4 per thread
    #pragma unroll
    for (int j = 0; j < 4; j++) {
        int ch = tid + j * 512;
        int n = ch >> 2, c = ch & 3;
        cpasync16(sptr(&sm->Bs[stage][n][c * 8]),
                  g_w1f_h + (size_t)n * DF_ + kb + c * 8);
    }
    cpcommit();
}

__global__ __launch_bounds__(512, 1) void logits_kernel(
    const float* __restrict__ feats, const float* __restrict__ w2)
{
    extern __shared__ char smem_raw[];
    SmemL* sm = (SmemL*)smem_raw;

    const int tid  = threadIdx.x;
    const int row0 = blockIdx.x * MT;
    const int b    = row0 >> 11;

    for (int i = tid; i < DM_; i += 512) {
        sm->eh[i]  = g_embh[b * DM_ + i];
        sm->w2s[i] = w2[i];
    }
    if (tid < MT) sm->logit[tid] = 0.f;

    // A tile: 128 rows x 8 float4 chunks = 1024 chunks, 2 per thread.
    const int r0c = tid >> 3,         c0 = tid & 7;          // chunk j=0
    const int r1c = (tid + 512) >> 3, c1 = (tid + 512) & 7;  // chunk j=1
    const float4* a_src0 = (const float4*)(feats + (size_t)(row0 + r0c) * DF_) + c0;
    const float4* a_src1 = (const float4*)(feats + (size_t)(row0 + r1c) * DF_) + c1;

    // Prologue: stage 0 (A via registers, B via cp.async group G0)
    {
        float4 v0 = a_src0[0];
        float4 v1 = a_src1[0];
        __half2 h0 = __floats2half2_rn(v0.x, v0.y);
        __half2 h1 = __floats2half2_rn(v0.z, v0.w);
        *(uint2*)&sm->As[0][r0c][c0 * 4] = make_uint2(*(unsigned*)&h0, *(unsigned*)&h1);
        h0 = __floats2half2_rn(v1.x, v1.y);
        h1 = __floats2half2_rn(v1.z, v1.w);
        *(uint2*)&sm->As[0][r1c][c1 * 4] = make_uint2(*(unsigned*)&h0, *(unsigned*)&h1);
    }
    load_B(sm, 0, 0, tid);

    const int lane   = tid & 31;
    const int wid    = tid >> 5;
    const int warp_m = wid & 1;
    const int warp_n = wid >> 1;
    const int g      = lane >> 2;
    const int t      = lane & 3;

    // ldmatrix per-lane source coordinates
    const int a_row = warp_m * 64 + (lane & 7) + ((lane >> 3) & 1) * 8;
    const int a_col = ((lane >> 4) & 1) * 8;
    const int b_row = warp_n * 64 + (lane & 7) + ((lane >> 4) & 1) * 8;
    const int b_col = ((lane >> 3) & 1) * 8;

    float C[4][8][4];
    #pragma unroll
    for (int mt = 0; mt < 4; mt++)
        #pragma unroll
        for (int nt = 0; nt < 8; nt++)
            #pragma unroll
            for (int i = 0; i < 4; i++) C[mt][nt][i] = 0.f;

    for (int it = 0; it < NIT; it++) {
        const int st    = it & 1;
        const int nxt   = st ^ 1;
        const bool more = (it + 1 < NIT);

        // LDG prefetch of the next A chunks (registers only — raceless)
        float4 av0, av1;
        if (more) {
            av0 = a_src0[(it + 1) * (KC / 4)];
            av1 = a_src1[(it + 1) * (KC / 4)];
        }

        cpwait<0>();       // G_it drained (only pending group)
        __syncthreads();   // all threads done reading buffer `nxt` (iter it-1)

        if (more) {
            load_B(sm, nxt, (it + 1) * KC, tid);   // commit G_{it+1}; overlaps mma below
            __half2 h0 = __floats2half2_rn(av0.x, av0.y);
            __half2 h1 = __floats2half2_rn(av0.z, av0.w);
            *(uint2*)&sm->As[nxt][r0c][c0 * 4] = make_uint2(*(unsigned*)&h0, *(unsigned*)&h1);
            h0 = __floats2half2_rn(av1.x, av1.y);
            h1 = __floats2half2_rn(av1.z, av1.w);
            *(uint2*)&sm->As[nxt][r1c][c1 * 4] = make_uint2(*(unsigned*)&h0, *(unsigned*)&h1);
        }

        #pragma unroll
        for (int ks = 0; ks < KC; ks += 16) {
            uint32_t a[4][4], bb[8][2];
            #pragma unroll
            for (int mt = 0; mt < 4; mt++)
                ldsm_x4(a[mt], &sm->As[st][a_row + mt * 16][a_col + ks]);
            #pragma unroll
            for (int p = 0; p < 4; p++) {
                uint32_t r[4];
                ldsm_x4(r, &sm->Bs[st][b_row + p * 16][b_col + ks]);
                bb[2 * p][0] = r[0]; bb[2 * p][1] = r[1];
                bb[2 * p + 1][0] = r[2]; bb[2 * p + 1][1] = r[3];
            }
            #pragma unroll
            for (int mt = 0; mt < 4; mt++)
                #pragma unroll
                for (int nt = 0; nt < 8; nt++)
                    mma_f16(C[mt][nt], a[mt], bb[nt]);
        }
    }
    __syncthreads();

    // Epilogue: logits[row] += sum_n w2[n]*tanh(C + emb_h[n])
    #pragma unroll
    for (int mt = 0; mt < 4; mt++) {
        float rs0 = 0.f, rs1 = 0.f;
        #pragma unroll
        for (int nt = 0; nt < 8; nt++) {
            int col = warp_n * 64 + nt * 8 + 2 * t;
            float e0 = sm->eh[col], e1 = sm->eh[col + 1];
            float wa = sm->w2s[col], wb = sm->w2s[col + 1];
            rs0 += tanh_fast(C[mt][nt][0] + e0) * wa + tanh_fast(C[mt][nt][1] + e1) * wb;
            rs1 += tanh_fast(C[mt][nt][2] + e0) * wa + tanh_fast(C[mt][nt][3] + e1) * wb;
        }
        // reduce over t (lanes within a quad hold disjoint columns)
        rs0 += __shfl_xor_sync(0xFFFFFFFFu, rs0, 1);
        rs0 += __shfl_xor_sync(0xFFFFFFFFu, rs0, 2);
        rs1 += __shfl_xor_sync(0xFFFFFFFFu, rs1, 1);
        rs1 += __shfl_xor_sync(0xFFFFFFFFu, rs1, 2);
        if (t == 0) {
            int r = warp_m * 64 + mt * 16 + g;
            atomicAdd(&sm->logit[r], rs0);
            atomicAdd(&sm->logit[r + 8], rs1);
        }
    }
    __syncthreads();
    if (tid < MT) g_logits[row0 + tid] = sm->logit[tid];
}

// ---------------------------------------------------------------------------
// Stage 2: row softmax over S=2048
// ---------------------------------------------------------------------------
__global__ __launch_bounds__(256) void softmax_kernel(float* __restrict__ out_probs)
{
    int b = blockIdx.x;
    int tid = threadIdx.x;
    __shared__ float red_max[8];
    __shared__ float red_sum[8];

    float v[8];
    float mx = -INFINITY;
    #pragma unroll
    for (int i = 0; i < 8; i++) {
        v[i] = g_logits[b * S_ + tid + i * 256];
        mx = fmaxf(mx, v[i]);
    }
    #pragma unroll
    for (int o = 16; o; o >>= 1) mx = fmaxf(mx, __shfl_xor_sync(0xFFFFFFFFu, mx, o));
    if ((tid & 31) == 0) red_max[tid >> 5] = mx;
    __syncthreads();
    mx = red_max[0];
    #pragma unroll
    for (int i = 1; i < 8; i++) mx = fmaxf(mx, red_max[i]);

    float s = 0.f;
    #pragma unroll
    for (int i = 0; i < 8; i++) { v[i] = expf(v[i] - mx); s += v[i]; }
    #pragma unroll
    for (int o = 16; o; o >>= 1) s += __shfl_xor_sync(0xFFFFFFFFu, s, o);
    if ((tid & 31) == 0) red_sum[tid >> 5] = s;
    __syncthreads();
    s = 0.f;
    #pragma unroll
    for (int i = 0; i < 8; i++) s += red_sum[i];
    float inv = 1.0f / s;
    #pragma unroll
    for (int i = 0; i < 8; i++)
        out_probs[b * S_ + tid + i * 256] = v[i] * inv;
}

// ---------------------------------------------------------------------------
// Stage 3: context[b,d] = sum_s probs[b,s]*feats[b,s,d].
// Grid (SSPLIT, B), each block does 128 s-rows over all 1024 d (float4/thread),
// atomicAdd into zeroed output. 512 blocks -> full chip occupancy.
// ---------------------------------------------------------------------------
#define SSPLIT 16
#define SCHUNK (S_ / SSPLIT)   // 128

__global__ __launch_bounds__(256) void context_kernel(
    const float4* __restrict__ feats4, const float* __restrict__ probs,
    float* __restrict__ out_ctx)
{
    int b  = blockIdx.y;
    int s0 = blockIdx.x * SCHUNK;
    int tid = threadIdx.x;

    __shared__ float p_s[SCHUNK];
    if (tid < SCHUNK) p_s[tid] = probs[b * S_ + s0 + tid];
    __syncthreads();

    const float4* f = feats4 + ((size_t)b * S_ + s0) * (DF_ / 4) + tid;
    float4 acc = make_float4(0.f, 0.f, 0.f, 0.f);
    #pragma unroll 4
    for (int j = 0; j < SCHUNK; j++) {
        float p = p_s[j];
        float4 v = f[(size_t)j * (DF_ / 4)];
        acc.x += p * v.x; acc.y += p * v.y; acc.z += p * v.z; acc.w += p * v.w;
    }
    float* o = out_ctx + b * DF_ + tid * 4;
    atomicAdd(o + 0, acc.x);
    atomicAdd(o + 1, acc.y);
    atomicAdd(o + 2, acc.z);
    atomicAdd(o + 3, acc.w);
}

// ---------------------------------------------------------------------------
// Launch
// ---------------------------------------------------------------------------
extern "C" void kernel_launch(void* const* d_in, const int* in_sizes, int n_in,
                              void* d_out, int out_size)
{
    const float* hidden = (const float*)d_in[0];
    const float* feats  = (const float*)d_in[1];
    const float* W1h    = (const float*)d_in[2];
    const float* b1h    = (const float*)d_in[3];
    const float* W1f    = (const float*)d_in[4];
    const float* b1f    = (const float*)d_in[5];
    const float* w2     = (const float*)d_in[6];

    float* out_ctx   = (float*)d_out;             // [32, 1024]
    float* out_probs = (float*)d_out + B_ * DF_;  // [32, 1, 2048]

    cvt_w1f_kernel<<<64, 512>>>((const float4*)W1f);
    embh_kernel<<<B_, 512>>>(hidden, W1h, b1h, b1f);

    cudaFuncSetAttribute(logits_kernel,
                         cudaFuncAttributeMaxDynamicSharedMemorySize,
                         (int)sizeof(SmemL));
    logits_kernel<<<(B_ * S_) / MT, 512, sizeof(SmemL)>>>(feats, w2);

    softmax_kernel<<<B_, 256>>>(out_probs);

    cudaMemsetAsync(out_ctx, 0, B_ * DF_ * sizeof(float));
    {
        dim3 grid(SSPLIT, B_);
        context_kernel<<<grid, 256>>>((const float4*)feats, out_probs, out_ctx);
    }
}

// round 9
// speedup vs baseline: 1.9079x; 1.9079x over previous
#include <cuda_runtime.h>
#include <cuda_fp16.h>
#include <math.h>
#include <stdint.h>

#define B_  32
#define S_  2048
#define DH_ 1024
#define DF_ 1024
#define DM_ 512

// Scratch (no cudaMalloc allowed)
__device__ float  g_embh[B_ * DM_];     // emb_h + b1h + b1f
__device__ float  g_logits[B_ * S_];    // pre-softmax logits
__device__ __half g_w1f_h[DM_ * DF_];   // 1 MiB half copy of W1f

// ---------------------------------------------------------------------------
// Helpers
// ---------------------------------------------------------------------------
__device__ __forceinline__ void mma_f16(float c[4], const uint32_t a[4], const uint32_t b[2]) {
    asm volatile(
        "mma.sync.aligned.m16n8k16.row.col.f32.f16.f16.f32 "
        "{%0,%1,%2,%3}, {%4,%5,%6,%7}, {%8,%9}, {%0,%1,%2,%3};"
        : "+f"(c[0]), "+f"(c[1]), "+f"(c[2]), "+f"(c[3])
        : "r"(a[0]), "r"(a[1]), "r"(a[2]), "r"(a[3]),
          "r"(b[0]), "r"(b[1]));
}

__device__ __forceinline__ unsigned sptr(const void* p) {
    return (unsigned)__cvta_generic_to_shared(p);
}

__device__ __forceinline__ void ldsm_x4(uint32_t r[4], const void* p) {
    unsigned a = sptr(p);
    asm volatile("ldmatrix.sync.aligned.m8n8.x4.shared.b16 {%0,%1,%2,%3}, [%4];"
                 : "=r"(r[0]), "=r"(r[1]), "=r"(r[2]), "=r"(r[3]) : "r"(a));
}

__device__ __forceinline__ float tanh_fast(float x) {
    // tanh(x) = 1 - 2/(exp(2x)+1), via ex2/rcp approx (rel err ~1e-6).
    float e;
    asm("ex2.approx.f32 %0, %1;" : "=f"(e) : "f"(x * 2.8853900817779268f));
    float r;
    asm("rcp.approx.f32 %0, %1;" : "=f"(r) : "f"(e + 1.0f));
    return 1.0f - 2.0f * r;
}

__device__ __forceinline__ void cpasync16(unsigned dst, const void* src) {
    asm volatile("cp.async.cg.shared.global [%0], [%1], 16;\n" :: "r"(dst), "l"(src));
}
__device__ __forceinline__ void cpcommit() { asm volatile("cp.async.commit_group;\n"); }
template<int N> __device__ __forceinline__ void cpwait() {
    asm volatile("cp.async.wait_group %0;\n" :: "n"(N));
}

// ---------------------------------------------------------------------------
// fp32 -> fp16 conversion of W1f only (1 MiB; feats converted in-register)
// ---------------------------------------------------------------------------
__global__ __launch_bounds__(512) void cvt_w1f_kernel(const float4* __restrict__ src)
{
    const int n4 = (DM_ * DF_) / 4;
    uint2* dst = (uint2*)g_w1f_h;
    int stride = gridDim.x * blockDim.x;
    for (int i = blockIdx.x * blockDim.x + threadIdx.x; i < n4; i += stride) {
        float4 v = src[i];
        __half2 h0 = __floats2half2_rn(v.x, v.y);
        __half2 h1 = __floats2half2_rn(v.z, v.w);
        dst[i] = make_uint2(*(unsigned*)&h0, *(unsigned*)&h1);
    }
}

// ---------------------------------------------------------------------------
// Stage 0: emb_h[b,m] = hidden[b,:]·W1h[m,:] + b1h[m] + b1f[m]
// ---------------------------------------------------------------------------
__global__ __launch_bounds__(512) void embh_kernel(
    const float* __restrict__ hidden, const float* __restrict__ W1h,
    const float* __restrict__ b1h, const float* __restrict__ b1f)
{
    int b = blockIdx.x;
    __shared__ float h_s[DH_];
    for (int k = threadIdx.x; k < DH_; k += 512) h_s[k] = hidden[b * DH_ + k];
    __syncthreads();

    int wid = threadIdx.x >> 5, lane = threadIdx.x & 31;
    for (int j = 0; j < DM_ / 16; j++) {
        int m = wid * (DM_ / 16) + j;
        const float* w = W1h + (size_t)m * DH_;
        float acc = 0.f;
        #pragma unroll 8
        for (int k = lane; k < DH_; k += 32) acc += h_s[k] * w[k];
        #pragma unroll
        for (int o = 16; o; o >>= 1) acc += __shfl_xor_sync(0xFFFFFFFFu, acc, o);
        if (lane == 0) g_embh[b * DM_ + m] = acc + b1h[m] + b1f[m];
    }
}

// ---------------------------------------------------------------------------
// Stage 1: fused logits. Block = 64 (b,s) rows x all 512 DM cols (R5 layout).
// fp16 m16n8k16, ldmatrix fragment loads.
// B (W1f): 3-stage cp.async ring, prefetch distance 2, wait_group<=1 so the
//          L2 refill latency is fully hidden behind the mma of prior iters.
// A (feats): fp32 LDG -> in-register cvt -> STS, double-buffered, written
//            only AFTER the barrier (race-safe, proven in R5).
// 16 warps: warp_m {0,1} x warp_n {0..7}, warp tile 32x64, C = 64 regs.
// ---------------------------------------------------------------------------
#define KC  32
#define KPH 40            // padded row stride in halves (80 B, conflict-free)
#define NIT (DF_ / KC)    // 32
#define BSTG 3            // B ring stages

struct SmemL {
    __half As[2][64][KPH];
    __half Bs[BSTG][512][KPH];
    float  eh[DM_];
    float  w2s[DM_];
    float  logit[64];
};

__device__ __forceinline__ void load_B(SmemL* sm, int stage, int kb, int tid) {
    // B tile: 512 rows x 32 halves = 2048 x 16B chunks, 4 per thread
    #pragma unroll
    for (int j = 0; j < 4; j++) {
        int ch = tid + j * 512;
        int n = ch >> 2, c = ch & 3;
        cpasync16(sptr(&sm->Bs[stage][n][c * 8]),
                  g_w1f_h + (size_t)n * DF_ + kb + c * 8);
    }
    cpcommit();
}

__global__ __launch_bounds__(512, 1) void logits_kernel(
    const float* __restrict__ feats, const float* __restrict__ w2)
{
    extern __shared__ char smem_raw[];
    SmemL* sm = (SmemL*)smem_raw;

    const int tid  = threadIdx.x;
    const int row0 = blockIdx.x * 64;
    const int b    = row0 >> 11;

    for (int i = tid; i < DM_; i += 512) {
        sm->eh[i]  = g_embh[b * DM_ + i];
        sm->w2s[i] = w2[i];
    }
    if (tid < 64) sm->logit[tid] = 0.f;

    // A tile addressing: thread -> (row = tid>>3, float4-chunk c = tid&7)
    const int ar = tid >> 3;
    const int ac = tid & 7;
    const float4* a_src = (const float4*)(feats + (size_t)(row0 + ar) * DF_) + ac;

    // Prologue: B groups G0, G1 (stages 0,1); A stage 0 direct.
    load_B(sm, 0, 0, tid);
    load_B(sm, 1, KC, tid);
    {
        float4 v = a_src[0];
        __half2 h0 = __floats2half2_rn(v.x, v.y);
        __half2 h1 = __floats2half2_rn(v.z, v.w);
        *(uint2*)&sm->As[0][ar][ac * 4] = make_uint2(*(unsigned*)&h0, *(unsigned*)&h1);
    }

    const int lane   = tid & 31;
    const int wid    = tid >> 5;
    const int warp_m = wid & 1;
    const int warp_n = wid >> 1;
    const int g      = lane >> 2;
    const int t      = lane & 3;

    // ldmatrix per-lane source coordinates
    const int a_row = warp_m * 32 + (lane & 7) + ((lane >> 3) & 1) * 8;
    const int a_col = ((lane >> 4) & 1) * 8;
    const int b_row = warp_n * 64 + (lane & 7) + ((lane >> 4) & 1) * 8;
    const int b_col = ((lane >> 3) & 1) * 8;

    float C[2][8][4];
    #pragma unroll
    for (int mt = 0; mt < 2; mt++)
        #pragma unroll
        for (int nt = 0; nt < 8; nt++)
            #pragma unroll
            for (int i = 0; i < 4; i++) C[mt][nt][i] = 0.f;

    int stB = 0;            // B ring stage for current iter
    for (int it = 0; it < NIT; it++) {
        const int stA   = it & 1;
        const bool more = (it + 1 < NIT);

        // LDG prefetch of the next A chunk (registers only — raceless)
        float4 av;
        if (more) av = a_src[(it + 1) * (KC / 4)];

        // Group for iter `it` was committed at it-2 (or prologue): with at most
        // one newer group allowed to remain in flight, it is guaranteed done.
        if (it == NIT - 1) cpwait<0>(); else cpwait<1>();
        __syncthreads();   // publish cp.async writes; all readers of reused bufs done

        if (it + 2 < NIT) {
            int st2 = stB + 2; if (st2 >= BSTG) st2 -= BSTG;
            load_B(sm, st2, (it + 2) * KC, tid);   // commit G_{it+2}; overlaps mma
        }
        if (more) {
            __half2 h0 = __floats2half2_rn(av.x, av.y);
            __half2 h1 = __floats2half2_rn(av.z, av.w);
            *(uint2*)&sm->As[stA ^ 1][ar][ac * 4] = make_uint2(*(unsigned*)&h0, *(unsigned*)&h1);
        }

        #pragma unroll
        for (int ks = 0; ks < KC; ks += 16) {
            uint32_t a[2][4], bb[8][2];
            #pragma unroll
            for (int mt = 0; mt < 2; mt++)
                ldsm_x4(a[mt], &sm->As[stA][a_row + mt * 16][a_col + ks]);
            #pragma unroll
            for (int p = 0; p < 4; p++) {
                uint32_t r[4];
                ldsm_x4(r, &sm->Bs[stB][b_row + p * 16][b_col + ks]);
                bb[2 * p][0] = r[0]; bb[2 * p][1] = r[1];
                bb[2 * p + 1][0] = r[2]; bb[2 * p + 1][1] = r[3];
            }
            #pragma unroll
            for (int mt = 0; mt < 2; mt++)
                #pragma unroll
                for (int nt = 0; nt < 8; nt++)
                    mma_f16(C[mt][nt], a[mt], bb[nt]);
        }

        if (++stB == BSTG) stB = 0;
    }
    __syncthreads();

    // Epilogue: logits[row] += sum_n w2[n]*tanh(C + emb_h[n])
    #pragma unroll
    for (int mt = 0; mt < 2; mt++) {
        float rs0 = 0.f, rs1 = 0.f;
        #pragma unroll
        for (int nt = 0; nt < 8; nt++) {
            int col = warp_n * 64 + nt * 8 + 2 * t;
            float e0 = sm->eh[col], e1 = sm->eh[col + 1];
            float wa = sm->w2s[col], wb = sm->w2s[col + 1];
            rs0 += tanh_fast(C[mt][nt][0] + e0) * wa + tanh_fast(C[mt][nt][1] + e1) * wb;
            rs1 += tanh_fast(C[mt][nt][2] + e0) * wa + tanh_fast(C[mt][nt][3] + e1) * wb;
        }
        // reduce over t (lanes within a quad hold disjoint columns)
        rs0 += __shfl_xor_sync(0xFFFFFFFFu, rs0, 1);
        rs0 += __shfl_xor_sync(0xFFFFFFFFu, rs0, 2);
        rs1 += __shfl_xor_sync(0xFFFFFFFFu, rs1, 1);
        rs1 += __shfl_xor_sync(0xFFFFFFFFu, rs1, 2);
        if (t == 0) {
            int r = warp_m * 32 + mt * 16 + g;
            atomicAdd(&sm->logit[r], rs0);
            atomicAdd(&sm->logit[r + 8], rs1);
        }
    }
    __syncthreads();
    if (tid < 64) g_logits[row0 + tid] = sm->logit[tid];
}

// ---------------------------------------------------------------------------
// Stage 2: row softmax over S=2048
// ---------------------------------------------------------------------------
__global__ __launch_bounds__(256) void softmax_kernel(float* __restrict__ out_probs)
{
    int b = blockIdx.x;
    int tid = threadIdx.x;
    __shared__ float red_max[8];
    __shared__ float red_sum[8];

    float v[8];
    float mx = -INFINITY;
    #pragma unroll
    for (int i = 0; i < 8; i++) {
        v[i] = g_logits[b * S_ + tid + i * 256];
        mx = fmaxf(mx, v[i]);
    }
    #pragma unroll
    for (int o = 16; o; o >>= 1) mx = fmaxf(mx, __shfl_xor_sync(0xFFFFFFFFu, mx, o));
    if ((tid & 31) == 0) red_max[tid >> 5] = mx;
    __syncthreads();
    mx = red_max[0];
    #pragma unroll
    for (int i = 1; i < 8; i++) mx = fmaxf(mx, red_max[i]);

    float s = 0.f;
    #pragma unroll
    for (int i = 0; i < 8; i++) { v[i] = expf(v[i] - mx); s += v[i]; }
    #pragma unroll
    for (int o = 16; o; o >>= 1) s += __shfl_xor_sync(0xFFFFFFFFu, s, o);
    if ((tid & 31) == 0) red_sum[tid >> 5] = s;
    __syncthreads();
    s = 0.f;
    #pragma unroll
    for (int i = 0; i < 8; i++) s += red_sum[i];
    float inv = 1.0f / s;
    #pragma unroll
    for (int i = 0; i < 8; i++)
        out_probs[b * S_ + tid + i * 256] = v[i] * inv;
}

// ---------------------------------------------------------------------------
// Stage 3: context[b,d] = sum_s probs[b,s]*feats[b,s,d].
// Grid (SSPLIT, B), atomicAdd into zeroed output. 1024 blocks.
// ---------------------------------------------------------------------------
#define SSPLIT 32
#define SCHUNK (S_ / SSPLIT)   // 64

__global__ __launch_bounds__(256) void context_kernel(
    const float4* __restrict__ feats4, const float* __restrict__ probs,
    float* __restrict__ out_ctx)
{
    int b  = blockIdx.y;
    int s0 = blockIdx.x * SCHUNK;
    int tid = threadIdx.x;

    __shared__ float p_s[SCHUNK];
    if (tid < SCHUNK) p_s[tid] = probs[b * S_ + s0 + tid];
    __syncthreads();

    const float4* f = feats4 + ((size_t)b * S_ + s0) * (DF_ / 4) + tid;
    float4 acc = make_float4(0.f, 0.f, 0.f, 0.f);
    #pragma unroll 4
    for (int j = 0; j < SCHUNK; j++) {
        float p = p_s[j];
        float4 v = f[(size_t)j * (DF_ / 4)];
        acc.x += p * v.x; acc.y += p * v.y; acc.z += p * v.z; acc.w += p * v.w;
    }
    float* o = out_ctx + b * DF_ + tid * 4;
    atomicAdd(o + 0, acc.x);
    atomicAdd(o + 1, acc.y);
    atomicAdd(o + 2, acc.z);
    atomicAdd(o + 3, acc.w);
}

// ---------------------------------------------------------------------------
// Launch
// ---------------------------------------------------------------------------
extern "C" void kernel_launch(void* const* d_in, const int* in_sizes, int n_in,
                              void* d_out, int out_size)
{
    const float* hidden = (const float*)d_in[0];
    const float* feats  = (const float*)d_in[1];
    const float* W1h    = (const float*)d_in[2];
    const float* b1h    = (const float*)d_in[3];
    const float* W1f    = (const float*)d_in[4];
    const float* b1f    = (const float*)d_in[5];
    const float* w2     = (const float*)d_in[6];

    float* out_ctx   = (float*)d_out;             // [32, 1024]
    float* out_probs = (float*)d_out + B_ * DF_;  // [32, 1, 2048]

    cvt_w1f_kernel<<<64, 512>>>((const float4*)W1f);
    embh_kernel<<<B_, 512>>>(hidden, W1h, b1h, b1f);

    cudaFuncSetAttribute(logits_kernel,
                         cudaFuncAttributeMaxDynamicSharedMemorySize,
                         (int)sizeof(SmemL));
    logits_kernel<<<(B_ * S_) / 64, 512, sizeof(SmemL)>>>(feats, w2);

    softmax_kernel<<<B_, 256>>>(out_probs);

    cudaMemsetAsync(out_ctx, 0, B_ * DF_ * sizeof(float));
    {
        dim3 grid(SSPLIT, B_);
        context_kernel<<<grid, 256>>>((const float4*)feats, out_probs, out_ctx);
    }
}

// round 16
// speedup vs baseline: 1.9592x; 1.0269x over previous
#include <cuda_runtime.h>
#include <cuda_fp16.h>
#include <math.h>
#include <stdint.h>

#define B_  32
#define S_  2048
#define DH_ 1024
#define DF_ 1024
#define DM_ 512

// Scratch (no cudaMalloc allowed)
__device__ float  g_embh[B_ * DM_];     // emb_h + b1h + b1f
__device__ float  g_logits[B_ * S_];    // pre-softmax logits
__device__ __half g_w1f_h[DM_ * DF_];   // 1 MiB half copy of W1f

// ---------------------------------------------------------------------------
// Helpers
// ---------------------------------------------------------------------------
__device__ __forceinline__ void mma_f16(float c[4], const uint32_t a[4], const uint32_t b[2]) {
    asm volatile(
        "mma.sync.aligned.m16n8k16.row.col.f32.f16.f16.f32 "
        "{%0,%1,%2,%3}, {%4,%5,%6,%7}, {%8,%9}, {%0,%1,%2,%3};"
        : "+f"(c[0]), "+f"(c[1]), "+f"(c[2]), "+f"(c[3])
        : "r"(a[0]), "r"(a[1]), "r"(a[2]), "r"(a[3]),
          "r"(b[0]), "r"(b[1]));
}

__device__ __forceinline__ unsigned sptr(const void* p) {
    return (unsigned)__cvta_generic_to_shared(p);
}

__device__ __forceinline__ void ldsm_x4(uint32_t r[4], const void* p) {
    unsigned a = sptr(p);
    asm volatile("ldmatrix.sync.aligned.m8n8.x4.shared.b16 {%0,%1,%2,%3}, [%4];"
                 : "=r"(r[0]), "=r"(r[1]), "=r"(r[2]), "=r"(r[3]) : "r"(a));
}

__device__ __forceinline__ float tanh_fast(float x) {
    // tanh(x) = 1 - 2/(exp(2x)+1), via ex2/rcp approx (rel err ~1e-6).
    float e;
    asm("ex2.approx.f32 %0, %1;" : "=f"(e) : "f"(x * 2.8853900817779268f));
    float r;
    asm("rcp.approx.f32 %0, %1;" : "=f"(r) : "f"(e + 1.0f));
    return 1.0f - 2.0f * r;
}

__device__ __forceinline__ void cpasync16(unsigned dst, const void* src) {
    asm volatile("cp.async.cg.shared.global [%0], [%1], 16;\n" :: "r"(dst), "l"(src));
}
__device__ __forceinline__ void cpcommit() { asm volatile("cp.async.commit_group;\n"); }
template<int N> __device__ __forceinline__ void cpwait() {
    asm volatile("cp.async.wait_group %0;\n" :: "n"(N));
}

// ---------------------------------------------------------------------------
// fp32 -> fp16 conversion of W1f only (1 MiB; feats converted in-register)
// ---------------------------------------------------------------------------
__global__ __launch_bounds__(512) void cvt_w1f_kernel(const float4* __restrict__ src)
{
    const int n4 = (DM_ * DF_) / 4;
    uint2* dst = (uint2*)g_w1f_h;
    int stride = gridDim.x * blockDim.x;
    for (int i = blockIdx.x * blockDim.x + threadIdx.x; i < n4; i += stride) {
        float4 v = src[i];
        __half2 h0 = __floats2half2_rn(v.x, v.y);
        __half2 h1 = __floats2half2_rn(v.z, v.w);
        dst[i] = make_uint2(*(unsigned*)&h0, *(unsigned*)&h1);
    }
}

// ---------------------------------------------------------------------------
// Stage 0: emb_h[b,m] = hidden[b,:]·W1h[m,:] + b1h[m] + b1f[m]
// ---------------------------------------------------------------------------
__global__ __launch_bounds__(512) void embh_kernel(
    const float* __restrict__ hidden, const float* __restrict__ W1h,
    const float* __restrict__ b1h, const float* __restrict__ b1f)
{
    int b = blockIdx.x;
    __shared__ float h_s[DH_];
    for (int k = threadIdx.x; k < DH_; k += 512) h_s[k] = hidden[b * DH_ + k];
    __syncthreads();

    int wid = threadIdx.x >> 5, lane = threadIdx.x & 31;
    for (int j = 0; j < DM_ / 16; j++) {
        int m = wid * (DM_ / 16) + j;
        const float* w = W1h + (size_t)m * DH_;
        float acc = 0.f;
        #pragma unroll 8
        for (int k = lane; k < DH_; k += 32) acc += h_s[k] * w[k];
        #pragma unroll
        for (int o = 16; o; o >>= 1) acc += __shfl_xor_sync(0xFFFFFFFFu, acc, o);
        if (lane == 0) g_embh[b * DM_ + m] = acc + b1h[m] + b1f[m];
    }
}

// ---------------------------------------------------------------------------
// Stage 1: fused logits. Block = 64 (b,s) rows x all 512 DM cols.
// fp16 m16n8k16, ldmatrix, cp.async double-buffered B, in-register A cvt.
// KEY CHANGE vs R5: the A-operand LDG (a DRAM miss, ~577 cyc) is issued
// right AFTER the barrier and consumed (cvt+STS) at the END of the iteration,
// so its latency is hidden behind the whole mma section instead of being
// exposed in the critical section right after the barrier.
// Race-safety unchanged: As[nxt]'s readers finished before this barrier;
// the next barrier publishes the STS before anyone reads it.
// 16 warps: warp_m {0,1} x warp_n {0..7}, warp tile 32x64, C = 64 regs.
// ---------------------------------------------------------------------------
#define KC  32
#define KPH 40            // padded row stride in halves (80 B, conflict-free)
#define NIT (DF_ / KC)    // 32

struct SmemL {
    __half As[2][64][KPH];
    __half Bs[2][512][KPH];
    float  eh[DM_];
    float  w2s[DM_];
    float  logit[64];
};

__device__ __forceinline__ void load_B(SmemL* sm, int stage, int kb, int tid) {
    // B tile: 512 rows x 32 halves = 2048 x 16B chunks, 4 per thread
    #pragma unroll
    for (int j = 0; j < 4; j++) {
        int ch = tid + j * 512;
        int n = ch >> 2, c = ch & 3;
        cpasync16(sptr(&sm->Bs[stage][n][c * 8]),
                  g_w1f_h + (size_t)n * DF_ + kb + c * 8);
    }
    cpcommit();
}

__global__ __launch_bounds__(512, 1) void logits_kernel(
    const float* __restrict__ feats, const float* __restrict__ w2)
{
    extern __shared__ char smem_raw[];
    SmemL* sm = (SmemL*)smem_raw;

    const int tid  = threadIdx.x;
    const int row0 = blockIdx.x * 64;
    const int b    = row0 >> 11;

    for (int i = tid; i < DM_; i += 512) {
        sm->eh[i]  = g_embh[b * DM_ + i];
        sm->w2s[i] = w2[i];
    }
    if (tid < 64) sm->logit[tid] = 0.f;

    // A tile addressing: thread -> (row = tid>>3, float4-chunk c = tid&7)
    const int ar = tid >> 3;
    const int ac = tid & 7;
    const float4* a_src = (const float4*)(feats + (size_t)(row0 + ar) * DF_) + ac;

    // Prologue: stage 0 (A direct, B via cp.async group G0)
    {
        float4 v = a_src[0];
        __half2 h0 = __floats2half2_rn(v.x, v.y);
        __half2 h1 = __floats2half2_rn(v.z, v.w);
        *(uint2*)&sm->As[0][ar][ac * 4] = make_uint2(*(unsigned*)&h0, *(unsigned*)&h1);
    }
    load_B(sm, 0, 0, tid);

    const int lane   = tid & 31;
    const int wid    = tid >> 5;
    const int warp_m = wid & 1;
    const int warp_n = wid >> 1;
    const int g      = lane >> 2;
    const int t      = lane & 3;

    // ldmatrix per-lane source coordinates
    const int a_row = warp_m * 32 + (lane & 7) + ((lane >> 3) & 1) * 8;
    const int a_col = ((lane >> 4) & 1) * 8;
    const int b_row = warp_n * 64 + (lane & 7) + ((lane >> 4) & 1) * 8;
    const int b_col = ((lane >> 3) & 1) * 8;

    float C[2][8][4];
    #pragma unroll
    for (int mt = 0; mt < 2; mt++)
        #pragma unroll
        for (int nt = 0; nt < 8; nt++)
            #pragma unroll
            for (int i = 0; i < 4; i++) C[mt][nt][i] = 0.f;

    for (int it = 0; it < NIT; it++) {
        const int st    = it & 1;
        const int nxt   = st ^ 1;
        const bool more = (it + 1 < NIT);

        cpwait<0>();       // G_it drained (only pending group)
        __syncthreads();   // all threads done reading buffer `nxt` (iter it-1)

        // Issue next-stage loads immediately after the barrier:
        //  - B via cp.async (group G_{it+1}); landed by cpwait next iter
        //  - A via LDG into registers; consumed by the STS *after* the mma
        //    section below, giving it ~the full mma latency to complete.
        float4 av;
        if (more) {
            load_B(sm, nxt, (it + 1) * KC, tid);
            av = a_src[(it + 1) * (KC / 4)];
        }

        #pragma unroll
        for (int ks = 0; ks < KC; ks += 16) {
            uint32_t a[2][4], bb[8][2];
            #pragma unroll
            for (int mt = 0; mt < 2; mt++)
                ldsm_x4(a[mt], &sm->As[st][a_row + mt * 16][a_col + ks]);
            #pragma unroll
            for (int p = 0; p < 4; p++) {
                uint32_t r[4];
                ldsm_x4(r, &sm->Bs[st][b_row + p * 16][b_col + ks]);
                bb[2 * p][0] = r[0]; bb[2 * p][1] = r[1];
                bb[2 * p + 1][0] = r[2]; bb[2 * p + 1][1] = r[3];
            }
            #pragma unroll
            for (int mt = 0; mt < 2; mt++)
                #pragma unroll
                for (int nt = 0; nt < 8; nt++)
                    mma_f16(C[mt][nt], a[mt], bb[nt]);
        }

        // Convert + store the prefetched A chunk (LDG has landed by now).
        if (more) {
            __half2 h0 = __floats2half2_rn(av.x, av.y);
            __half2 h1 = __floats2half2_rn(av.z, av.w);
            *(uint2*)&sm->As[nxt][ar][ac * 4] = make_uint2(*(unsigned*)&h0, *(unsigned*)&h1);
        }
    }
    __syncthreads();

    // Epilogue: logits[row] += sum_n w2[n]*tanh(C + emb_h[n])
    #pragma unroll
    for (int mt = 0; mt < 2; mt++) {
        float rs0 = 0.f, rs1 = 0.f;
        #pragma unroll
        for (int nt = 0; nt < 8; nt++) {
            int col = warp_n * 64 + nt * 8 + 2 * t;
            float e0 = sm->eh[col], e1 = sm->eh[col + 1];
            float wa = sm->w2s[col], wb = sm->w2s[col + 1];
            rs0 += tanh_fast(C[mt][nt][0] + e0) * wa + tanh_fast(C[mt][nt][1] + e1) * wb;
            rs1 += tanh_fast(C[mt][nt][2] + e0) * wa + tanh_fast(C[mt][nt][3] + e1) * wb;
        }
        // reduce over t (lanes within a quad hold disjoint columns)
        rs0 += __shfl_xor_sync(0xFFFFFFFFu, rs0, 1);
        rs0 += __shfl_xor_sync(0xFFFFFFFFu, rs0, 2);
        rs1 += __shfl_xor_sync(0xFFFFFFFFu, rs1, 1);
        rs1 += __shfl_xor_sync(0xFFFFFFFFu, rs1, 2);
        if (t == 0) {
            int r = warp_m * 32 + mt * 16 + g;
            atomicAdd(&sm->logit[r], rs0);
            atomicAdd(&sm->logit[r + 8], rs1);
        }
    }
    __syncthreads();
    if (tid < 64) g_logits[row0 + tid] = sm->logit[tid];
}

// ---------------------------------------------------------------------------
// Stage 2: row softmax over S=2048
// ---------------------------------------------------------------------------
__global__ __launch_bounds__(256) void softmax_kernel(float* __restrict__ out_probs)
{
    int b = blockIdx.x;
    int tid = threadIdx.x;
    __shared__ float red_max[8];
    __shared__ float red_sum[8];

    float v[8];
    float mx = -INFINITY;
    #pragma unroll
    for (int i = 0; i < 8; i++) {
        v[i] = g_logits[b * S_ + tid + i * 256];
        mx = fmaxf(mx, v[i]);
    }
    #pragma unroll
    for (int o = 16; o; o >>= 1) mx = fmaxf(mx, __shfl_xor_sync(0xFFFFFFFFu, mx, o));
    if ((tid & 31) == 0) red_max[tid >> 5] = mx;
    __syncthreads();
    mx = red_max[0];
    #pragma unroll
    for (int i = 1; i < 8; i++) mx = fmaxf(mx, red_max[i]);

    float s = 0.f;
    #pragma unroll
    for (int i = 0; i < 8; i++) { v[i] = expf(v[i] - mx); s += v[i]; }
    #pragma unroll
    for (int o = 16; o; o >>= 1) s += __shfl_xor_sync(0xFFFFFFFFu, s, o);
    if ((tid & 31) == 0) red_sum[tid >> 5] = s;
    __syncthreads();
    s = 0.f;
    #pragma unroll
    for (int i = 0; i < 8; i++) s += red_sum[i];
    float inv = 1.0f / s;
    #pragma unroll
    for (int i = 0; i < 8; i++)
        out_probs[b * S_ + tid + i * 256] = v[i] * inv;
}

// ---------------------------------------------------------------------------
// Stage 3: context[b,d] = sum_s probs[b,s]*feats[b,s,d].
// Grid (SSPLIT, B), atomicAdd into zeroed output. 512 blocks.
// ---------------------------------------------------------------------------
#define SSPLIT 16
#define SCHUNK (S_ / SSPLIT)   // 128

__global__ __launch_bounds__(256) void context_kernel(
    const float4* __restrict__ feats4, const float* __restrict__ probs,
    float* __restrict__ out_ctx)
{
    int b  = blockIdx.y;
    int s0 = blockIdx.x * SCHUNK;
    int tid = threadIdx.x;

    __shared__ float p_s[SCHUNK];
    if (tid < SCHUNK) p_s[tid] = probs[b * S_ + s0 + tid];
    __syncthreads();

    const float4* f = feats4 + ((size_t)b * S_ + s0) * (DF_ / 4) + tid;
    float4 acc = make_float4(0.f, 0.f, 0.f, 0.f);
    #pragma unroll 4
    for (int j = 0; j < SCHUNK; j++) {
        float p = p_s[j];
        float4 v = f[(size_t)j * (DF_ / 4)];
        acc.x += p * v.x; acc.y += p * v.y; acc.z += p * v.z; acc.w += p * v.w;
    }
    float* o = out_ctx + b * DF_ + tid * 4;
    atomicAdd(o + 0, acc.x);
    atomicAdd(o + 1, acc.y);
    atomicAdd(o + 2, acc.z);
    atomicAdd(o + 3, acc.w);
}

// ---------------------------------------------------------------------------
// Launch
// ---------------------------------------------------------------------------
extern "C" void kernel_launch(void* const* d_in, const int* in_sizes, int n_in,
                              void* d_out, int out_size)
{
    const float* hidden = (const float*)d_in[0];
    const float* feats  = (const float*)d_in[1];
    const float* W1h    = (const float*)d_in[2];
    const float* b1h    = (const float*)d_in[3];
    const float* W1f    = (const float*)d_in[4];
    const float* b1f    = (const float*)d_in[5];
    const float* w2     = (const float*)d_in[6];

    float* out_ctx   = (float*)d_out;             // [32, 1024]
    float* out_probs = (float*)d_out + B_ * DF_;  // [32, 1, 2048]

    cvt_w1f_kernel<<<64, 512>>>((const float4*)W1f);
    embh_kernel<<<B_, 512>>>(hidden, W1h, b1h, b1f);

    cudaFuncSetAttribute(logits_kernel,
                         cudaFuncAttributeMaxDynamicSharedMemorySize,
                         (int)sizeof(SmemL));
    logits_kernel<<<(B_ * S_) / 64, 512, sizeof(SmemL)>>>(feats, w2);

    softmax_kernel<<<B_, 256>>>(out_probs);

    cudaMemsetAsync(out_ctx, 0, B_ * DF_ * sizeof(float));
    {
        dim3 grid(SSPLIT, B_);
        context_kernel<<<grid, 256>>>((const float4*)feats, out_probs, out_ctx);
    }
}

// round 17
// speedup vs baseline: 2.1350x; 1.0897x over previous
#include <cuda_runtime.h>
#include <cuda_fp16.h>
#include <math.h>
#include <stdint.h>

#define B_  32
#define S_  2048
#define DH_ 1024
#define DF_ 1024
#define DM_ 512

// Scratch (no cudaMalloc allowed)
__device__ float  g_embh[B_ * DM_];     // emb_h + b1h + b1f
__device__ float  g_logits[B_ * S_];    // pre-softmax logits
__device__ __half g_w1f_h[DM_ * DF_];   // 1 MiB half copy of W1f

// ---------------------------------------------------------------------------
// Helpers
// ---------------------------------------------------------------------------
__device__ __forceinline__ void mma_f16(float c[4], const uint32_t a[4], const uint32_t b[2]) {
    asm volatile(
        "mma.sync.aligned.m16n8k16.row.col.f32.f16.f16.f32 "
        "{%0,%1,%2,%3}, {%4,%5,%6,%7}, {%8,%9}, {%0,%1,%2,%3};"
        : "+f"(c[0]), "+f"(c[1]), "+f"(c[2]), "+f"(c[3])
        : "r"(a[0]), "r"(a[1]), "r"(a[2]), "r"(a[3]),
          "r"(b[0]), "r"(b[1]));
}

__device__ __forceinline__ unsigned sptr(const void* p) {
    return (unsigned)__cvta_generic_to_shared(p);
}

__device__ __forceinline__ void ldsm_x4(uint32_t r[4], const void* p) {
    unsigned a = sptr(p);
    asm volatile("ldmatrix.sync.aligned.m8n8.x4.shared.b16 {%0,%1,%2,%3}, [%4];"
                 : "=r"(r[0]), "=r"(r[1]), "=r"(r[2]), "=r"(r[3]) : "r"(a));
}

__device__ __forceinline__ float tanh_fast(float x) {
    // tanh(x) = 1 - 2/(exp(2x)+1), via ex2/rcp approx (rel err ~1e-6).
    float e;
    asm("ex2.approx.f32 %0, %1;" : "=f"(e) : "f"(x * 2.8853900817779268f));
    float r;
    asm("rcp.approx.f32 %0, %1;" : "=f"(r) : "f"(e + 1.0f));
    return 1.0f - 2.0f * r;
}

__device__ __forceinline__ void cpasync16(unsigned dst, const void* src) {
    asm volatile("cp.async.cg.shared.global [%0], [%1], 16;\n" :: "r"(dst), "l"(src));
}
__device__ __forceinline__ void cpcommit() { asm volatile("cp.async.commit_group;\n"); }
template<int N> __device__ __forceinline__ void cpwait() {
    asm volatile("cp.async.wait_group %0;\n" :: "n"(N));
}

// ---------------------------------------------------------------------------
// fp32 -> fp16 conversion of W1f only (1 MiB; feats converted in-register)
// ---------------------------------------------------------------------------
__global__ __launch_bounds__(512) void cvt_w1f_kernel(const float4* __restrict__ src)
{
    const int n4 = (DM_ * DF_) / 4;
    uint2* dst = (uint2*)g_w1f_h;
    int stride = gridDim.x * blockDim.x;
    for (int i = blockIdx.x * blockDim.x + threadIdx.x; i < n4; i += stride) {
        float4 v = src[i];
        __half2 h0 = __floats2half2_rn(v.x, v.y);
        __half2 h1 = __floats2half2_rn(v.z, v.w);
        dst[i] = make_uint2(*(unsigned*)&h0, *(unsigned*)&h1);
    }
}

// ---------------------------------------------------------------------------
// Stage 0: emb_h[b,m] = hidden[b,:]·W1h[m,:] + b1h[m] + b1f[m]
// ---------------------------------------------------------------------------
__global__ __launch_bounds__(512) void embh_kernel(
    const float* __restrict__ hidden, const float* __restrict__ W1h,
    const float* __restrict__ b1h, const float* __restrict__ b1f)
{
    int b = blockIdx.x;
    __shared__ float h_s[DH_];
    for (int k = threadIdx.x; k < DH_; k += 512) h_s[k] = hidden[b * DH_ + k];
    __syncthreads();

    int wid = threadIdx.x >> 5, lane = threadIdx.x & 31;
    for (int j = 0; j < DM_ / 16; j++) {
        int m = wid * (DM_ / 16) + j;
        const float* w = W1h + (size_t)m * DH_;
        float acc = 0.f;
        #pragma unroll 8
        for (int k = lane; k < DH_; k += 32) acc += h_s[k] * w[k];
        #pragma unroll
        for (int o = 16; o; o >>= 1) acc += __shfl_xor_sync(0xFFFFFFFFu, acc, o);
        if (lane == 0) g_embh[b * DM_ + m] = acc + b1h[m] + b1f[m];
    }
}

// ---------------------------------------------------------------------------
// Stage 1: fused logits. Block = 64 (b,s) rows x all 512 DM cols.
// fp16 m16n8k16, ldmatrix, cp.async double-buffered B, in-register A cvt.
// KEY CHANGE vs R15: KC 32 -> 64. The per-iteration fixed overhead
// (barrier spread, cp.async drain, pipeline refill) proved to be the binder
// (all latency-hiding variants were neutral); halving the iteration count
// (32 -> 16) halves that tax while accumulator pressure is unchanged.
// KPH=72 (144 B row stride): bank delta/row = 36 = 4 mod 32 -> the 8 lanes
// of an ldsm phase cover disjoint bank quads -> conflict-free.
// 16 warps: warp_m {0,1} x warp_n {0..7}, warp tile 32x64, C = 64 regs.
// ---------------------------------------------------------------------------
#define KC  64
#define KPH 72
#define NIT (DF_ / KC)    // 16

struct SmemL {
    __half As[2][64][KPH];     // 18432 B
    __half Bs[2][512][KPH];    // 147456 B
    float  eh[DM_];            // 2048 B
    float  w2s[DM_];           // 2048 B
    float  logit[64];          // 256 B
};                             // = 170240 B total

__device__ __forceinline__ void load_B(SmemL* sm, int stage, int kb, int tid) {
    // B tile: 512 rows x 64 halves = 4096 x 16B chunks, 8 per thread
    #pragma unroll
    for (int j = 0; j < 8; j++) {
        int ch = tid + j * 512;
        int n = ch >> 3, c = ch & 7;
        cpasync16(sptr(&sm->Bs[stage][n][c * 8]),
                  g_w1f_h + (size_t)n * DF_ + kb + c * 8);
    }
    cpcommit();
}

__global__ __launch_bounds__(512, 1) void logits_kernel(
    const float* __restrict__ feats, const float* __restrict__ w2)
{
    extern __shared__ char smem_raw[];
    SmemL* sm = (SmemL*)smem_raw;

    const int tid  = threadIdx.x;
    const int row0 = blockIdx.x * 64;
    const int b    = row0 >> 11;

    for (int i = tid; i < DM_; i += 512) {
        sm->eh[i]  = g_embh[b * DM_ + i];
        sm->w2s[i] = w2[i];
    }
    if (tid < 64) sm->logit[tid] = 0.f;

    // A tile: 64 rows x 16 float4 chunks = 1024 chunks, 2 per thread.
    const int r0 = tid >> 4;          // rows 0..31
    const int c0 = tid & 15;          // float4 chunk within KC=64 (16 floats... 16 chunks)
    const int r1 = r0 + 32;           // rows 32..63
    const float4* a_src0 = (const float4*)(feats + (size_t)(row0 + r0) * DF_) + c0;
    const float4* a_src1 = (const float4*)(feats + (size_t)(row0 + r1) * DF_) + c0;

    // Prologue: stage 0 (A direct, B via cp.async group G0)
    {
        float4 v0 = a_src0[0];
        float4 v1 = a_src1[0];
        __half2 h0 = __floats2half2_rn(v0.x, v0.y);
        __half2 h1 = __floats2half2_rn(v0.z, v0.w);
        *(uint2*)&sm->As[0][r0][c0 * 4] = make_uint2(*(unsigned*)&h0, *(unsigned*)&h1);
        h0 = __floats2half2_rn(v1.x, v1.y);
        h1 = __floats2half2_rn(v1.z, v1.w);
        *(uint2*)&sm->As[0][r1][c0 * 4] = make_uint2(*(unsigned*)&h0, *(unsigned*)&h1);
    }
    load_B(sm, 0, 0, tid);

    const int lane   = tid & 31;
    const int wid    = tid >> 5;
    const int warp_m = wid & 1;
    const int warp_n = wid >> 1;
    const int g      = lane >> 2;
    const int t      = lane & 3;

    // ldmatrix per-lane source coordinates
    const int a_row = warp_m * 32 + (lane & 7) + ((lane >> 3) & 1) * 8;
    const int a_col = ((lane >> 4) & 1) * 8;
    const int b_row = warp_n * 64 + (lane & 7) + ((lane >> 4) & 1) * 8;
    const int b_col = ((lane >> 3) & 1) * 8;

    float C[2][8][4];
    #pragma unroll
    for (int mt = 0; mt < 2; mt++)
        #pragma unroll
        for (int nt = 0; nt < 8; nt++)
            #pragma unroll
            for (int i = 0; i < 4; i++) C[mt][nt][i] = 0.f;

    for (int it = 0; it < NIT; it++) {
        const int st    = it & 1;
        const int nxt   = st ^ 1;
        const bool more = (it + 1 < NIT);

        cpwait<0>();       // G_it drained (only pending group)
        __syncthreads();   // all threads done reading buffer `nxt` (iter it-1)

        // Issue next-stage loads right after the barrier; A LDG is consumed
        // by the STS after the (long) mma section -> latency fully covered.
        float4 av0, av1;
        if (more) {
            load_B(sm, nxt, (it + 1) * KC, tid);
            av0 = a_src0[(it + 1) * (KC / 4)];
            av1 = a_src1[(it + 1) * (KC / 4)];
        }

        #pragma unroll
        for (int ks = 0; ks < KC; ks += 16) {
            uint32_t a[2][4], bb[8][2];
            #pragma unroll
            for (int mt = 0; mt < 2; mt++)
                ldsm_x4(a[mt], &sm->As[st][a_row + mt * 16][a_col + ks]);
            #pragma unroll
            for (int p = 0; p < 4; p++) {
                uint32_t r[4];
                ldsm_x4(r, &sm->Bs[st][b_row + p * 16][b_col + ks]);
                bb[2 * p][0] = r[0]; bb[2 * p][1] = r[1];
                bb[2 * p + 1][0] = r[2]; bb[2 * p + 1][1] = r[3];
            }
            #pragma unroll
            for (int mt = 0; mt < 2; mt++)
                #pragma unroll
                for (int nt = 0; nt < 8; nt++)
                    mma_f16(C[mt][nt], a[mt], bb[nt]);
        }

        // Convert + store the prefetched A chunks (LDGs have landed by now).
        if (more) {
            __half2 h0 = __floats2half2_rn(av0.x, av0.y);
            __half2 h1 = __floats2half2_rn(av0.z, av0.w);
            *(uint2*)&sm->As[nxt][r0][c0 * 4] = make_uint2(*(unsigned*)&h0, *(unsigned*)&h1);
            h0 = __floats2half2_rn(av1.x, av1.y);
            h1 = __floats2half2_rn(av1.z, av1.w);
            *(uint2*)&sm->As[nxt][r1][c0 * 4] = make_uint2(*(unsigned*)&h0, *(unsigned*)&h1);
        }
    }
    __syncthreads();

    // Epilogue: logits[row] += sum_n w2[n]*tanh(C + emb_h[n])
    #pragma unroll
    for (int mt = 0; mt < 2; mt++) {
        float rs0 = 0.f, rs1 = 0.f;
        #pragma unroll
        for (int nt = 0; nt < 8; nt++) {
            int col = warp_n * 64 + nt * 8 + 2 * t;
            float e0 = sm->eh[col], e1 = sm->eh[col + 1];
            float wa = sm->w2s[col], wb = sm->w2s[col + 1];
            rs0 += tanh_fast(C[mt][nt][0] + e0) * wa + tanh_fast(C[mt][nt][1] + e1) * wb;
            rs1 += tanh_fast(C[mt][nt][2] + e0) * wa + tanh_fast(C[mt][nt][3] + e1) * wb;
        }
        // reduce over t (lanes within a quad hold disjoint columns)
        rs0 += __shfl_xor_sync(0xFFFFFFFFu, rs0, 1);
        rs0 += __shfl_xor_sync(0xFFFFFFFFu, rs0, 2);
        rs1 += __shfl_xor_sync(0xFFFFFFFFu, rs1, 1);
        rs1 += __shfl_xor_sync(0xFFFFFFFFu, rs1, 2);
        if (t == 0) {
            int r = warp_m * 32 + mt * 16 + g;
            atomicAdd(&sm->logit[r], rs0);
            atomicAdd(&sm->logit[r + 8], rs1);
        }
    }
    __syncthreads();
    if (tid < 64) g_logits[row0 + tid] = sm->logit[tid];
}

// ---------------------------------------------------------------------------
// Stage 2: row softmax over S=2048
// ---------------------------------------------------------------------------
__global__ __launch_bounds__(256) void softmax_kernel(float* __restrict__ out_probs)
{
    int b = blockIdx.x;
    int tid = threadIdx.x;
    __shared__ float red_max[8];
    __shared__ float red_sum[8];

    float v[8];
    float mx = -INFINITY;
    #pragma unroll
    for (int i = 0; i < 8; i++) {
        v[i] = g_logits[b * S_ + tid + i * 256];
        mx = fmaxf(mx, v[i]);
    }
    #pragma unroll
    for (int o = 16; o; o >>= 1) mx = fmaxf(mx, __shfl_xor_sync(0xFFFFFFFFu, mx, o));
    if ((tid & 31) == 0) red_max[tid >> 5] = mx;
    __syncthreads();
    mx = red_max[0];
    #pragma unroll
    for (int i = 1; i < 8; i++) mx = fmaxf(mx, red_max[i]);

    float s = 0.f;
    #pragma unroll
    for (int i = 0; i < 8; i++) { v[i] = expf(v[i] - mx); s += v[i]; }
    #pragma unroll
    for (int o = 16; o; o >>= 1) s += __shfl_xor_sync(0xFFFFFFFFu, s, o);
    if ((tid & 31) == 0) red_sum[tid >> 5] = s;
    __syncthreads();
    s = 0.f;
    #pragma unroll
    for (int i = 0; i < 8; i++) s += red_sum[i];
    float inv = 1.0f / s;
    #pragma unroll
    for (int i = 0; i < 8; i++)
        out_probs[b * S_ + tid + i * 256] = v[i] * inv;
}

// ---------------------------------------------------------------------------
// Stage 3: context[b,d] = sum_s probs[b,s]*feats[b,s,d].
// Grid (SSPLIT, B), atomicAdd into zeroed output. 512 blocks.
// ---------------------------------------------------------------------------
#define SSPLIT 16
#define SCHUNK (S_ / SSPLIT)   // 128

__global__ __launch_bounds__(256) void context_kernel(
    const float4* __restrict__ feats4, const float* __restrict__ probs,
    float* __restrict__ out_ctx)
{
    int b  = blockIdx.y;
    int s0 = blockIdx.x * SCHUNK;
    int tid = threadIdx.x;

    __shared__ float p_s[SCHUNK];
    if (tid < SCHUNK) p_s[tid] = probs[b * S_ + s0 + tid];
    __syncthreads();

    const float4* f = feats4 + ((size_t)b * S_ + s0) * (DF_ / 4) + tid;
    float4 acc = make_float4(0.f, 0.f, 0.f, 0.f);
    #pragma unroll 4
    for (int j = 0; j < SCHUNK; j++) {
        float p = p_s[j];
        float4 v = f[(size_t)j * (DF_ / 4)];
        acc.x += p * v.x; acc.y += p * v.y; acc.z += p * v.z; acc.w += p * v.w;
    }
    float* o = out_ctx + b * DF_ + tid * 4;
    atomicAdd(o + 0, acc.x);
    atomicAdd(o + 1, acc.y);
    atomicAdd(o + 2, acc.z);
    atomicAdd(o + 3, acc.w);
}

// ---------------------------------------------------------------------------
// Launch
// ---------------------------------------------------------------------------
extern "C" void kernel_launch(void* const* d_in, const int* in_sizes, int n_in,
                              void* d_out, int out_size)
{
    const float* hidden = (const float*)d_in[0];
    const float* feats  = (const float*)d_in[1];
    const float* W1h    = (const float*)d_in[2];
    const float* b1h    = (const float*)d_in[3];
    const float* W1f    = (const float*)d_in[4];
    const float* b1f    = (const float*)d_in[5];
    const float* w2     = (const float*)d_in[6];

    float* out_ctx   = (float*)d_out;             // [32, 1024]
    float* out_probs = (float*)d_out + B_ * DF_;  // [32, 1, 2048]

    cvt_w1f_kernel<<<64, 512>>>((const float4*)W1f);
    embh_kernel<<<B_, 512>>>(hidden, W1h, b1h, b1f);

    cudaFuncSetAttribute(logits_kernel,
                         cudaFuncAttributeMaxDynamicSharedMemorySize,
                         (int)sizeof(SmemL));
    logits_kernel<<<(B_ * S_) / 64, 512, sizeof(SmemL)>>>(feats, w2);

    softmax_kernel<<<B_, 256>>>(out_probs);

    cudaMemsetAsync(out_ctx, 0, B_ * DF_ * sizeof(float));
    {
        dim3 grid(SSPLIT, B_);
        context_kernel<<<grid, 256>>>((const float4*)feats, out_probs, out_ctx);
    }
}